// round 14
// baseline (speedup 1.0000x reference)
#include <cuda_runtime.h>
#include <cuda_fp16.h>
#include <cstdint>
#include <math.h>

#define BB    512
#define STATE 256
#define DES   128
#define H     512
#define SPLITS 18
#define STG   8      // fp32 B ring stages (thread-private roundtrip)

// smem layout (bytes):
//   [0, 4096)    scale table (8 chunks x 16 recs x 8 u32)
//   [4096, ...)  fp32 B rings: 4 pairs x STG x (16 x 32 f32 = 2048B)
//   then         h2 B tiles:   4 pairs x 3 bufs x (16 rows x 80B = 1280B)
#define SC_BYTES   4096
#define RING_OFF   SC_BYTES
#define PAIR_RING  (STG * 2048)                  // 16384
#define H2_OFF     (RING_OFF + 4 * PAIR_RING)    // 69632
#define PAIR_H2    (3 * 1280)                    // 3840
#define SMEM_BYTES (H2_OFF + 4 * PAIR_H2)        // 84992 -> 2 CTAs/SM

__device__ uint32_t g_h0[BB * H / 2];
__device__ uint32_t g_h1[BB * H / 2];
__device__ float g_part[SPLITS][BB][H];

__device__ __forceinline__ uint32_t pack_h2(float lo, float hi) {
    uint32_t r;
    asm("cvt.rn.f16x2.f32 %0, %1, %2;" : "=r"(r) : "f"(hi), "f"(lo));
    return r;
}
__device__ __forceinline__ uint32_t hmul2(uint32_t a, uint32_t b) {
    uint32_t r;
    asm("mul.rn.f16x2 %0, %1, %2;" : "=r"(r) : "r"(a), "r"(b));
    return r;
}
__device__ __forceinline__ uint32_t dup_h2(float s) {
    uint32_t r;
    asm("{ .reg .b16 h; cvt.rn.f16.f32 h, %1; mov.b32 %0, {h, h}; }" : "=r"(r) : "f"(s));
    return r;
}
__device__ __forceinline__ void mma16816(float* c,
                                         uint32_t a0, uint32_t a1, uint32_t a2, uint32_t a3,
                                         uint32_t b0, uint32_t b1) {
    asm volatile("mma.sync.aligned.m16n8k16.row.col.f32.f16.f16.f32 "
                 "{%0,%1,%2,%3}, {%4,%5,%6,%7}, {%8,%9}, {%0,%1,%2,%3};"
                 : "+f"(c[0]), "+f"(c[1]), "+f"(c[2]), "+f"(c[3])
                 : "r"(a0), "r"(a1), "r"(a2), "r"(a3), "r"(b0), "r"(b1));
}
__device__ __forceinline__ uint32_t smem_u32(const void* p) {
    uint32_t a;
    asm("{ .reg .u64 t; cvta.to.shared.u64 t, %1; cvt.u32.u64 %0, t; }" : "=r"(a) : "l"(p));
    return a;
}
__device__ __forceinline__ void cp16(uint32_t dst, const float* src) {
    asm volatile("cp.async.cg.shared.global [%0], [%1], 16;" :: "r"(dst), "l"(src));
}
__device__ __forceinline__ float4 lds128f(uint32_t a) {
    float4 v;
    asm volatile("ld.shared.v4.f32 {%0,%1,%2,%3}, [%4];"
                 : "=f"(v.x), "=f"(v.y), "=f"(v.z), "=f"(v.w) : "r"(a));
    return v;
}
__device__ __forceinline__ void sts64(uint32_t a, uint32_t x, uint32_t y) {
    asm volatile("st.shared.v2.b32 [%0], {%1,%2};" :: "r"(a), "r"(x), "r"(y) : "memory");
}
__device__ __forceinline__ void ldsm4t(uint32_t& b0, uint32_t& b1, uint32_t& b2, uint32_t& b3,
                                       uint32_t addr) {
    asm volatile("ldmatrix.sync.aligned.m8n8.x4.trans.shared.b16 {%0,%1,%2,%3}, [%4];"
                 : "=r"(b0), "=r"(b1), "=r"(b2), "=r"(b3) : "r"(addr));
}
#define CP_COMMIT() asm volatile("cp.async.commit_group;" ::: "memory")
#define CP_WAIT5()  asm volatile("cp.async.wait_group 5;" ::: "memory")
#define CP_WAIT6()  asm volatile("cp.async.wait_group 6;" ::: "memory")

// ---------------------------------------------------------------------------
__global__ void embed_kernel(const float* __restrict__ state,
                             const float* __restrict__ ew,
                             const float* __restrict__ eb) {
    int idx = blockIdx.x * blockDim.x + threadIdx.x;
    int b = idx >> 8;
    int j = (idx & 255) * 2;
    float s0 = eb[j], s1 = eb[j + 1];
    const float* sp = state + b * STATE;
#pragma unroll 8
    for (int k = 0; k < STATE; k++) {
        float sv = sp[k];
        s0 = fmaf(sv, ew[k * H + j], s0);
        s1 = fmaf(sv, ew[k * H + j + 1], s1);
    }
    g_h0[idx] = pack_h2(tanhf(s0), tanhf(s1));
}

// ---------------------------------------------------------------------------
// fp16 m16n8k16 split-K GEMM, warp-pair-decoupled:
//  - B pipeline fully owned by warp PAIRS (pair wn = warps {2wn, 2wn+1}):
//    own fp32 cp.async ring slice (thread-private roundtrip -> no barrier),
//    pair-private h2 tile, pair-scoped named barrier (64 threads).
//    NO CTA-wide barrier in the mainloop.
//  - A: h2 activations in regs (one gmem load per k-band), scaled by HMUL2.
// ---------------------------------------------------------------------------
__global__ void __launch_bounds__(256, 2)
gemm_fp16(int layer, const float* __restrict__ cmd,
          const float* __restrict__ hwW, const float* __restrict__ hwb)
{
    extern __shared__ __align__(16) uint32_t smu[];
    uint32_t* sSc = smu;

    const int t    = threadIdx.x;
    const int lane = t & 31;
    const int w    = t >> 5;
    const int wm   = w & 1;
    const int wn   = w >> 1;
    const int q    = lane & 3;
    const int r4   = lane >> 2;

    const int n0 = blockIdx.x * 128;
    const int m0 = blockIdx.y * 128;
    const int sp = blockIdx.z;
    const int c0  = sp * 7 + (sp < 3 ? sp : 3);
    const int cnt = 7 + (sp < 3 ? 1 : 0);

    const uint32_t* __restrict__ inh = layer ? g_h1 : g_h0;

    // ---- scale table (CTA init, one barrier) ----
    if (t < cnt * 16) {
        int ci = t >> 4, rec = t & 15;
        int wmv = rec >> 3, rv = rec & 7;
        int d = c0 + ci;
        uint32_t* dst = sSc + (size_t)t * 8;
#pragma unroll
        for (int mi = 0; mi < 4; mi++) {
            int row0 = m0 + wmv * 64 + mi * 16 + rv;
            dst[mi * 2]     = dup_h2((d < DES) ? cmd[row0 * DES + d] : 1.0f);
            dst[mi * 2 + 1] = dup_h2((d < DES) ? cmd[(row0 + 8) * DES + d] : 1.0f);
        }
    }
    __syncthreads();

    const uint32_t base = smem_u32(smu);

    // ---- pair-private fp32 ring (thread-private roundtrip) ----
    const int krow_cp = wm * 8 + (lane >> 2);       // k row this thread copies
    const int nc8 = (lane & 3) * 8;                 // n offset within pair's 32 cols
    const uint32_t ringp = base + RING_OFF + (uint32_t)wn * PAIR_RING;
    const uint32_t rdst = ringp + (uint32_t)(krow_cp * 128 + nc8 * 4);

    // ---- pair-private h2 tile ----
    const uint32_t h2p = base + H2_OFF + (uint32_t)wn * PAIR_H2;
    const uint32_t csts = h2p + (uint32_t)krow_cp * 80 + (uint32_t)(lane & 3) * 16;
    // ldmatrix lane address (16x16 b16 per call; 2 calls cover 32 n-halfwords)
    const int sel  = lane >> 3;
    const int krow = ((sel & 1) << 3) | (lane & 7);
    const uint32_t ldm0 = h2p + (uint32_t)krow * 80 + (uint32_t)((sel >> 1) << 4);

    const int gsrc_off = n0 + wn * 32 + nc8;        // gmem col base for this thread

    auto issueB = [&](int kbj, int cij, int slot) {
        int d = c0 + cij;
        const float* bb = ((d < DES) ? (hwW + (size_t)d * (H * H)) : hwb)
                          + ((size_t)(kbj * 16 + krow_cp)) * H + gsrc_off;
        uint32_t dst = rdst + (uint32_t)slot * 2048;
        cp16(dst, bb);
        cp16(dst + 16, bb + 4);
        CP_COMMIT();
    };
    auto convert = [&](int slot, int buf3) {
        float4 v = lds128f(rdst + (uint32_t)slot * 2048);
        float4 u = lds128f(rdst + (uint32_t)slot * 2048 + 16);
        uint32_t dst = csts + (uint32_t)buf3 * 1280;
        sts64(dst, pack_h2(v.x, v.y), pack_h2(v.z, v.w));
        sts64(dst + 8, pack_h2(u.x, u.y), pack_h2(u.z, u.w));
    };

    float acc[4][4][4];
#pragma unroll
    for (int i = 0; i < 4; i++)
#pragma unroll
        for (int j = 0; j < 4; j++)
#pragma unroll
            for (int k = 0; k < 4; k++) acc[i][j][k] = 0.0f;

    // prologue: 7 stages in flight; convert stage 0 -> h2 buf 0
#pragma unroll
    for (int i = 0; i < 7; i++) issueB(0, i, i);
    int kb_is = 0, ci_is = 7;
    if (ci_is >= cnt) { ci_is -= cnt; kb_is = 1; }
    CP_WAIT6();
    convert(0, 0);
    asm volatile("bar.sync %0, %1;" :: "r"(1 + wn), "r"(64) : "memory");

    const uint32_t* aptr = inh + (size_t)(m0 + wm * 64 + r4) * (H / 2) + q;
    const uint32_t screc = (uint32_t)(wm * 8 + r4) * 8;

    uint32_t auf[4][4];
    int it = 0;
    int cur3 = 0, nxt3 = 1;

    for (int kb = 0; kb < 32; kb++) {
        // A band (h2) from gmem (L2-hot)
#pragma unroll
        for (int mi = 0; mi < 4; mi++) {
            const uint32_t* p = aptr + (size_t)(mi * 16) * (H / 2) + kb * 8;
            auf[mi][0] = p[0];
            auf[mi][1] = p[8 * (H / 2)];
            auf[mi][2] = p[4];
            auf[mi][3] = p[8 * (H / 2) + 4];
        }

        for (int ci = 0; ci < cnt; ci++, it++) {
            // convert stage it+1 into h2 buf nxt3 (thread-private fp32 read)
            CP_WAIT5();
            convert((it + 1) % STG, nxt3);

            // pair-scoped barrier: h2 buf nxt3 visible to both warps of pair
            asm volatile("bar.sync %0, %1;" :: "r"(1 + wn), "r"(64) : "memory");

            issueB(kb_is, ci_is, (it + 7) % STG);
            if (++ci_is == cnt) {
                ci_is = 0;
                if (++kb_is == 32) { kb_is = 31; ci_is = cnt - 1; }
            }

            // scale record: 2 broadcast LDS.128
            const uint4* rec = (const uint4*)(sSc + ((uint32_t)ci * 16 * 8 + screc));
            uint4 sA01 = rec[0];
            uint4 sA23 = rec[1];
            uint32_t sv[8] = {sA01.x, sA01.y, sA01.z, sA01.w,
                              sA23.x, sA23.y, sA23.z, sA23.w};

            // B fragments: 2x ldmatrix.x4.trans from pair h2 buf cur3
            uint32_t bf[4][2];
            {
                uint32_t a0 = ldm0 + (uint32_t)cur3 * 1280;
                ldsm4t(bf[0][0], bf[0][1], bf[1][0], bf[1][1], a0);
                ldsm4t(bf[2][0], bf[2][1], bf[3][0], bf[3][1], a0 + 32);
            }

            // scaled A + MMAs
#pragma unroll
            for (int mi = 0; mi < 4; mi++) {
                uint32_t s0 = sv[mi * 2], s1 = sv[mi * 2 + 1];
                uint32_t a0 = hmul2(auf[mi][0], s0);
                uint32_t a1 = hmul2(auf[mi][1], s1);
                uint32_t a2 = hmul2(auf[mi][2], s0);
                uint32_t a3 = hmul2(auf[mi][3], s1);
#pragma unroll
                for (int ni = 0; ni < 4; ni++)
                    mma16816(acc[mi][ni], a0, a1, a2, a3, bf[ni][0], bf[ni][1]);
            }

            cur3 = nxt3;
            nxt3 = (nxt3 == 2) ? 0 : nxt3 + 1;
        }
    }

    // epilogue
#pragma unroll
    for (int mi = 0; mi < 4; mi++) {
#pragma unroll
        for (int ni = 0; ni < 4; ni++) {
            int row = m0 + wm * 64 + mi * 16 + r4;
            int col = n0 + wn * 32 + ni * 8 + q * 2;
            *(float2*)&g_part[sp][row][col]     = make_float2(acc[mi][ni][0], acc[mi][ni][1]);
            *(float2*)&g_part[sp][row + 8][col] = make_float2(acc[mi][ni][2], acc[mi][ni][3]);
        }
    }
}

// ---------------------------------------------------------------------------
__global__ void reduce_bias_relu(const float* __restrict__ cmd,
                                 const float* __restrict__ hbW,
                                 const float* __restrict__ hbb,
                                 float* dst, int to_h1) {
    int idx = blockIdx.x * blockDim.x + threadIdx.x;
    int b = idx >> 8;
    int o = (idx & 255) * 2;
    float s0 = hbb[o], s1 = hbb[o + 1];
#pragma unroll
    for (int sp = 0; sp < SPLITS; sp++) {
        float2 v = *(const float2*)&g_part[sp][b][o];
        s0 += v.x; s1 += v.y;
    }
    const float* cp = cmd + b * DES;
#pragma unroll 16
    for (int k = 0; k < DES; k++) {
        float cv = cp[k];
        s0 = fmaf(cv, hbW[k * H + o], s0);
        s1 = fmaf(cv, hbW[k * H + o + 1], s1);
    }
    float r0 = fmaxf(s0, 0.0f);
    float r1 = fmaxf(s1, 0.0f);
    if (to_h1) {
        g_h1[idx] = pack_h2(r0, r1);
    } else {
        *(float2*)&dst[b * H + o] = make_float2(r0, r1);
    }
}

// ---------------------------------------------------------------------------
extern "C" void kernel_launch(void* const* d_in, const int* in_sizes, int n_in,
                              void* d_out, int out_size) {
    const float* state = (const float*)d_in[0];
    const float* cmd   = (const float*)d_in[1];
    const float* ew    = (const float*)d_in[2];
    const float* eb    = (const float*)d_in[3];
    const float* hwW   = (const float*)d_in[4];
    const float* hwb   = (const float*)d_in[5];
    const float* hbW   = (const float*)d_in[6];
    const float* hbb   = (const float*)d_in[7];
    float* out = (float*)d_out;

    const size_t HWW_L = (size_t)DES * H * H;
    const size_t HWB_L = (size_t)H * H;
    const size_t HBW_L = (size_t)DES * H;
    const size_t HBB_L = (size_t)H;

    static int smem_set = 0;
    if (!smem_set) {
        cudaFuncSetAttribute(gemm_fp16, cudaFuncAttributeMaxDynamicSharedMemorySize, SMEM_BYTES);
        smem_set = 1;
    }

    embed_kernel<<<512, 256>>>(state, ew, eb);

    dim3 grid(4, 4, SPLITS);

    gemm_fp16<<<grid, 256, SMEM_BYTES>>>(0, cmd, hwW, hwb);
    reduce_bias_relu<<<512, 256>>>(cmd, hbW, hbb, out, 1);

    gemm_fp16<<<grid, 256, SMEM_BYTES>>>(1, cmd, hwW + HWW_L, hwb + HWB_L);
    reduce_bias_relu<<<512, 256>>>(cmd, hbW + HBW_L, hbb + HBB_L, out, 0);
}

// round 16
// speedup vs baseline: 1.0096x; 1.0096x over previous
#include <cuda_runtime.h>
#include <cuda_fp16.h>
#include <cstdint>
#include <math.h>

#define BB    512
#define STATE 256
#define DES   128
#define H     512
#define SPLITS 18
#define STG   8      // fp32 B ring stages per wn-group

// smem layout (bytes):
//   [0, 8192)      scale table (8 chunks x 32 recs x 8 u32)
//   [8192, 73728)  fp32 B rings: 4 groups x STG x (16 x 32 f32 = 2KB)
//   [73728, ...)   h2 B tiles: 4 groups x 3 bufs x (16 rows x 80B = 1280B)
#define SC_BYTES   8192
#define RING_OFF   SC_BYTES
#define GROUP_RING (STG * 2048)                  // 16384
#define H2_OFF     (RING_OFF + 4 * GROUP_RING)   // 73728
#define H2ROW      80                            // 16-B multiple (ldmatrix align!)
#define H2BUF      (16 * H2ROW)                  // 1280
#define GROUP_H2   (3 * H2BUF)                   // 3840
#define SMEM_BYTES (H2_OFF + 4 * GROUP_H2)       // 89088 -> 1 CTA/SM (512 thr)

__device__ uint32_t g_h0[BB * H / 2];
__device__ uint32_t g_h1[BB * H / 2];
__device__ float g_part[SPLITS][BB][H];

__device__ __forceinline__ uint32_t pack_h2(float lo, float hi) {
    uint32_t r;
    asm("cvt.rn.f16x2.f32 %0, %1, %2;" : "=r"(r) : "f"(hi), "f"(lo));
    return r;
}
__device__ __forceinline__ uint32_t hmul2(uint32_t a, uint32_t b) {
    uint32_t r;
    asm("mul.rn.f16x2 %0, %1, %2;" : "=r"(r) : "r"(a), "r"(b));
    return r;
}
__device__ __forceinline__ uint32_t dup_h2(float s) {
    uint32_t r;
    asm("{ .reg .b16 h; cvt.rn.f16.f32 h, %1; mov.b32 %0, {h, h}; }" : "=r"(r) : "f"(s));
    return r;
}
__device__ __forceinline__ void mma16816(float* c,
                                         uint32_t a0, uint32_t a1, uint32_t a2, uint32_t a3,
                                         uint32_t b0, uint32_t b1) {
    asm volatile("mma.sync.aligned.m16n8k16.row.col.f32.f16.f16.f32 "
                 "{%0,%1,%2,%3}, {%4,%5,%6,%7}, {%8,%9}, {%0,%1,%2,%3};"
                 : "+f"(c[0]), "+f"(c[1]), "+f"(c[2]), "+f"(c[3])
                 : "r"(a0), "r"(a1), "r"(a2), "r"(a3), "r"(b0), "r"(b1));
}
__device__ __forceinline__ uint32_t smem_u32(const void* p) {
    uint32_t a;
    asm("{ .reg .u64 t; cvta.to.shared.u64 t, %1; cvt.u32.u64 %0, t; }" : "=r"(a) : "l"(p));
    return a;
}
__device__ __forceinline__ void cp16(uint32_t dst, const float* src) {
    asm volatile("cp.async.cg.shared.global [%0], [%1], 16;" :: "r"(dst), "l"(src));
}
__device__ __forceinline__ float4 lds128f(uint32_t a) {
    float4 v;
    asm volatile("ld.shared.v4.f32 {%0,%1,%2,%3}, [%4];"
                 : "=f"(v.x), "=f"(v.y), "=f"(v.z), "=f"(v.w) : "r"(a));
    return v;
}
__device__ __forceinline__ void sts64(uint32_t a, uint32_t x, uint32_t y) {
    asm volatile("st.shared.v2.b32 [%0], {%1,%2};" :: "r"(a), "r"(x), "r"(y) : "memory");
}
__device__ __forceinline__ void ldsm4t(uint32_t& b0, uint32_t& b1, uint32_t& b2, uint32_t& b3,
                                       uint32_t addr) {
    asm volatile("ldmatrix.sync.aligned.m8n8.x4.trans.shared.b16 {%0,%1,%2,%3}, [%4];"
                 : "=r"(b0), "=r"(b1), "=r"(b2), "=r"(b3) : "r"(addr));
}
#define CP_COMMIT() asm volatile("cp.async.commit_group;" ::: "memory")
#define CP_WAIT5()  asm volatile("cp.async.wait_group 5;" ::: "memory")
#define CP_WAIT6()  asm volatile("cp.async.wait_group 6;" ::: "memory")

// ---------------------------------------------------------------------------
__global__ void embed_kernel(const float* __restrict__ state,
                             const float* __restrict__ ew,
                             const float* __restrict__ eb) {
    int idx = blockIdx.x * blockDim.x + threadIdx.x;
    int b = idx >> 8;
    int j = (idx & 255) * 2;
    float s0 = eb[j], s1 = eb[j + 1];
    const float* sp = state + b * STATE;
#pragma unroll 8
    for (int k = 0; k < STATE; k++) {
        float sv = sp[k];
        s0 = fmaf(sv, ew[k * H + j], s0);
        s1 = fmaf(sv, ew[k * H + j + 1], s1);
    }
    g_h0[idx] = pack_h2(tanhf(s0), tanhf(s1));
}

// ---------------------------------------------------------------------------
// fp16 m16n8k16 split-K GEMM, 256x128 CTA tile (512 threads, 16 warps 4x4).
//  - B pipeline owned by wn-GROUPS (128 contiguous threads): own fp32 cp.async
//    ring slice (thread-private roundtrip), group-private h2 tile,
//    group-scoped named barrier. No CTA-wide barrier in mainloop.
//  - A: h2 activations in regs (one gmem load per k-band), scaled by HMUL2.
//  - B DRAM/L2 traffic HALVED vs 128-row tiles (2 m-tiles instead of 4).
// ---------------------------------------------------------------------------
__global__ void __launch_bounds__(512, 1)
gemm_fp16(int layer, const float* __restrict__ cmd,
          const float* __restrict__ hwW, const float* __restrict__ hwb)
{
    extern __shared__ __align__(16) uint32_t smu[];
    uint32_t* sSc = smu;

    const int t    = threadIdx.x;
    const int lane = t & 31;
    const int wm   = (t >> 5) & 3;   // 0..3 -> 64-row group
    const int wn   = t >> 7;         // 0..3 -> 32-col group (contiguous 128 thr)
    const int tg   = t & 127;        // thread-in-group
    const int q    = lane & 3;
    const int r4   = lane >> 2;

    const int n0 = blockIdx.x * 128;
    const int m0 = blockIdx.y * 256;
    const int sp = blockIdx.z;
    const int c0  = sp * 7 + (sp < 3 ? sp : 3);
    const int cnt = 7 + (sp < 3 ? 1 : 0);

    const uint32_t* __restrict__ inh = layer ? g_h1 : g_h0;

    // ---- scale table: rec(ci, wm*8+r4) = 8 u32 dup-h2 ----
    if (t < cnt * 32) {
        int ci = t >> 5, rec = t & 31;
        int wmv = rec >> 3, rv = rec & 7;
        int d = c0 + ci;
        uint32_t* dst = sSc + (size_t)t * 8;
#pragma unroll
        for (int mi = 0; mi < 4; mi++) {
            int row0 = m0 + wmv * 64 + mi * 16 + rv;
            dst[mi * 2]     = dup_h2((d < DES) ? cmd[row0 * DES + d] : 1.0f);
            dst[mi * 2 + 1] = dup_h2((d < DES) ? cmd[(row0 + 8) * DES + d] : 1.0f);
        }
    }
    __syncthreads();

    const uint32_t base = smem_u32(smu);

    // ---- group-private fp32 ring (thread-private roundtrip) ----
    const int krow_cp = tg >> 3;                // 0..15
    const int nco = (tg & 7) * 4;               // f32 col offset within 32
    const uint32_t ringp = base + RING_OFF + (uint32_t)wn * GROUP_RING;
    const uint32_t rdst = ringp + (uint32_t)(krow_cp * 32 + nco) * 4;

    // ---- group-private h2 tile (stride 80B = 16B multiple, ldsm conflict-free) ----
    const uint32_t h2p = base + H2_OFF + (uint32_t)wn * GROUP_H2;
    const uint32_t csts = h2p + (uint32_t)krow_cp * H2ROW + (uint32_t)(tg & 7) * 8;
    const int sel  = lane >> 3;
    const int krow = ((sel & 1) << 3) | (lane & 7);
    const uint32_t ldm0 = h2p + (uint32_t)krow * H2ROW + (uint32_t)((sel >> 1) << 4);

    const int gcol = n0 + wn * 32 + nco;

    auto issueB = [&](int kbj, int cij, int slot) {
        int d = c0 + cij;
        const float* bb = ((d < DES) ? (hwW + (size_t)d * (H * H)) : hwb)
                          + ((size_t)(kbj * 16 + krow_cp)) * H + gcol;
        cp16(rdst + (uint32_t)slot * 2048, bb);
        CP_COMMIT();
    };
    auto convert = [&](int slot, int buf3) {
        float4 v = lds128f(rdst + (uint32_t)slot * 2048);
        sts64(csts + (uint32_t)buf3 * H2BUF, pack_h2(v.x, v.y), pack_h2(v.z, v.w));
    };

    float acc[4][4][4];
#pragma unroll
    for (int i = 0; i < 4; i++)
#pragma unroll
        for (int j = 0; j < 4; j++)
#pragma unroll
            for (int k = 0; k < 4; k++) acc[i][j][k] = 0.0f;

    // prologue: 7 stages in flight; convert stage 0 -> h2 buf 0
#pragma unroll
    for (int i = 0; i < 7; i++) issueB(0, i, i);
    int kb_is = 0, ci_is = 7;
    if (ci_is >= cnt) { ci_is -= cnt; kb_is = 1; }
    CP_WAIT6();
    convert(0, 0);
    asm volatile("bar.sync %0, %1;" :: "r"(1 + wn), "r"(128) : "memory");

    const uint32_t* aptr = inh + (size_t)(m0 + wm * 64 + r4) * (H / 2) + q;
    const uint32_t screc = (uint32_t)(wm * 8 + r4) * 8;

    uint32_t auf[4][4];
    int it = 0;
    int cur3 = 0, nxt3 = 1;

    for (int kb = 0; kb < 32; kb++) {
        // A band (h2) from gmem (L2-hot)
#pragma unroll
        for (int mi = 0; mi < 4; mi++) {
            const uint32_t* p = aptr + (size_t)(mi * 16) * (H / 2) + kb * 8;
            auf[mi][0] = p[0];
            auf[mi][1] = p[8 * (H / 2)];
            auf[mi][2] = p[4];
            auf[mi][3] = p[8 * (H / 2) + 4];
        }

        for (int ci = 0; ci < cnt; ci++, it++) {
            // convert stage it+1 into h2 buf nxt3 (thread-private fp32 read)
            CP_WAIT5();
            convert((it + 1) % STG, nxt3);

            // group-scoped barrier: h2 buf nxt3 visible to the 4 warps of group
            asm volatile("bar.sync %0, %1;" :: "r"(1 + wn), "r"(128) : "memory");

            issueB(kb_is, ci_is, (it + 7) % STG);
            if (++ci_is == cnt) {
                ci_is = 0;
                if (++kb_is == 32) { kb_is = 31; ci_is = cnt - 1; }
            }

            // scale record: 2 broadcast LDS.128
            const uint4* rec = (const uint4*)(sSc + ((uint32_t)ci * 32 * 8 + screc));
            uint4 sA01 = rec[0];
            uint4 sA23 = rec[1];
            uint32_t sv[8] = {sA01.x, sA01.y, sA01.z, sA01.w,
                              sA23.x, sA23.y, sA23.z, sA23.w};

            // B fragments: 2x ldmatrix.x4.trans from group h2 buf cur3
            uint32_t bf[4][2];
            {
                uint32_t a0 = ldm0 + (uint32_t)cur3 * H2BUF;
                ldsm4t(bf[0][0], bf[0][1], bf[1][0], bf[1][1], a0);
                ldsm4t(bf[2][0], bf[2][1], bf[3][0], bf[3][1], a0 + 32);
            }

            // scaled A + MMAs
#pragma unroll
            for (int mi = 0; mi < 4; mi++) {
                uint32_t s0 = sv[mi * 2], s1 = sv[mi * 2 + 1];
                uint32_t a0 = hmul2(auf[mi][0], s0);
                uint32_t a1 = hmul2(auf[mi][1], s1);
                uint32_t a2 = hmul2(auf[mi][2], s0);
                uint32_t a3 = hmul2(auf[mi][3], s1);
#pragma unroll
                for (int ni = 0; ni < 4; ni++)
                    mma16816(acc[mi][ni], a0, a1, a2, a3, bf[ni][0], bf[ni][1]);
            }

            cur3 = nxt3;
            nxt3 = (nxt3 == 2) ? 0 : nxt3 + 1;
        }
    }

    // epilogue
#pragma unroll
    for (int mi = 0; mi < 4; mi++) {
#pragma unroll
        for (int ni = 0; ni < 4; ni++) {
            int row = m0 + wm * 64 + mi * 16 + r4;
            int col = n0 + wn * 32 + ni * 8 + q * 2;
            *(float2*)&g_part[sp][row][col]     = make_float2(acc[mi][ni][0], acc[mi][ni][1]);
            *(float2*)&g_part[sp][row + 8][col] = make_float2(acc[mi][ni][2], acc[mi][ni][3]);
        }
    }
}

// ---------------------------------------------------------------------------
__global__ void reduce_bias_relu(const float* __restrict__ cmd,
                                 const float* __restrict__ hbW,
                                 const float* __restrict__ hbb,
                                 float* dst, int to_h1) {
    int idx = blockIdx.x * blockDim.x + threadIdx.x;
    int b = idx >> 8;
    int o = (idx & 255) * 2;
    float s0 = hbb[o], s1 = hbb[o + 1];
#pragma unroll
    for (int sp = 0; sp < SPLITS; sp++) {
        float2 v = *(const float2*)&g_part[sp][b][o];
        s0 += v.x; s1 += v.y;
    }
    const float* cp = cmd + b * DES;
#pragma unroll 16
    for (int k = 0; k < DES; k++) {
        float cv = cp[k];
        s0 = fmaf(cv, hbW[k * H + o], s0);
        s1 = fmaf(cv, hbW[k * H + o + 1], s1);
    }
    float r0 = fmaxf(s0, 0.0f);
    float r1 = fmaxf(s1, 0.0f);
    if (to_h1) {
        g_h1[idx] = pack_h2(r0, r1);
    } else {
        *(float2*)&dst[b * H + o] = make_float2(r0, r1);
    }
}

// ---------------------------------------------------------------------------
extern "C" void kernel_launch(void* const* d_in, const int* in_sizes, int n_in,
                              void* d_out, int out_size) {
    const float* state = (const float*)d_in[0];
    const float* cmd   = (const float*)d_in[1];
    const float* ew    = (const float*)d_in[2];
    const float* eb    = (const float*)d_in[3];
    const float* hwW   = (const float*)d_in[4];
    const float* hwb   = (const float*)d_in[5];
    const float* hbW   = (const float*)d_in[6];
    const float* hbb   = (const float*)d_in[7];
    float* out = (float*)d_out;

    const size_t HWW_L = (size_t)DES * H * H;
    const size_t HWB_L = (size_t)H * H;
    const size_t HBW_L = (size_t)DES * H;
    const size_t HBB_L = (size_t)H;

    static int smem_set = 0;
    if (!smem_set) {
        cudaFuncSetAttribute(gemm_fp16, cudaFuncAttributeMaxDynamicSharedMemorySize, SMEM_BYTES);
        smem_set = 1;
    }

    embed_kernel<<<512, 256>>>(state, ew, eb);

    dim3 grid(4, 2, SPLITS);

    gemm_fp16<<<grid, 512, SMEM_BYTES>>>(0, cmd, hwW, hwb);
    reduce_bias_relu<<<512, 256>>>(cmd, hbW, hbb, out, 1);

    gemm_fp16<<<grid, 512, SMEM_BYTES>>>(1, cmd, hwW + HWW_L, hwb + HWB_L);
    reduce_bias_relu<<<512, 256>>>(cmd, hbW + HBW_L, hbb + HBB_L, out, 0);
}

// round 17
// speedup vs baseline: 1.0357x; 1.0258x over previous
#include <cuda_runtime.h>
#include <cuda_fp16.h>
#include <cstdint>
#include <math.h>

#define BB    512
#define STATE 256
#define DES   128
#define H     512
#define SPLITS 18
#define STG   8      // fp32 B ring stages per wn-group

// smem layout (bytes):
//   [0, 8192)      scale table (8 chunks x 32 recs x 8 u32)
//   [8192, 73728)  fp32 B rings: 4 groups x STG x (16 x 32 f32 = 2KB)
//   [73728, ...)   h2 B tiles: 4 groups x 4 bufs x (16 rows x 80B = 1280B)
#define SC_BYTES   8192
#define RING_OFF   SC_BYTES
#define GROUP_RING (STG * 2048)                  // 16384
#define H2_OFF     (RING_OFF + 4 * GROUP_RING)   // 73728
#define H2ROW      80                            // 16-B multiple (ldmatrix align)
#define H2BUF      (16 * H2ROW)                  // 1280
#define GROUP_H2   (4 * H2BUF)                   // 5120 (quad buffer)
#define SMEM_BYTES (H2_OFF + 4 * GROUP_H2)       // 94208 -> 1 CTA/SM (512 thr)

__device__ uint32_t g_h0[BB * H / 2];
__device__ uint32_t g_h1[BB * H / 2];
__device__ float g_part[SPLITS][BB][H];

__device__ __forceinline__ uint32_t pack_h2(float lo, float hi) {
    uint32_t r;
    asm("cvt.rn.f16x2.f32 %0, %1, %2;" : "=r"(r) : "f"(hi), "f"(lo));
    return r;
}
__device__ __forceinline__ uint32_t hmul2(uint32_t a, uint32_t b) {
    uint32_t r;
    asm("mul.rn.f16x2 %0, %1, %2;" : "=r"(r) : "r"(a), "r"(b));
    return r;
}
__device__ __forceinline__ uint32_t dup_h2(float s) {
    uint32_t r;
    asm("{ .reg .b16 h; cvt.rn.f16.f32 h, %1; mov.b32 %0, {h, h}; }" : "=r"(r) : "f"(s));
    return r;
}
__device__ __forceinline__ void mma16816(float* c,
                                         uint32_t a0, uint32_t a1, uint32_t a2, uint32_t a3,
                                         uint32_t b0, uint32_t b1) {
    asm volatile("mma.sync.aligned.m16n8k16.row.col.f32.f16.f16.f32 "
                 "{%0,%1,%2,%3}, {%4,%5,%6,%7}, {%8,%9}, {%0,%1,%2,%3};"
                 : "+f"(c[0]), "+f"(c[1]), "+f"(c[2]), "+f"(c[3])
                 : "r"(a0), "r"(a1), "r"(a2), "r"(a3), "r"(b0), "r"(b1));
}
__device__ __forceinline__ uint32_t smem_u32(const void* p) {
    uint32_t a;
    asm("{ .reg .u64 t; cvta.to.shared.u64 t, %1; cvt.u32.u64 %0, t; }" : "=r"(a) : "l"(p));
    return a;
}
__device__ __forceinline__ void cp16(uint32_t dst, const float* src) {
    asm volatile("cp.async.cg.shared.global [%0], [%1], 16;" :: "r"(dst), "l"(src));
}
__device__ __forceinline__ float4 lds128f(uint32_t a) {
    float4 v;
    asm volatile("ld.shared.v4.f32 {%0,%1,%2,%3}, [%4];"
                 : "=f"(v.x), "=f"(v.y), "=f"(v.z), "=f"(v.w) : "r"(a));
    return v;
}
__device__ __forceinline__ void sts64(uint32_t a, uint32_t x, uint32_t y) {
    asm volatile("st.shared.v2.b32 [%0], {%1,%2};" :: "r"(a), "r"(x), "r"(y) : "memory");
}
__device__ __forceinline__ void ldsm4t(uint32_t& b0, uint32_t& b1, uint32_t& b2, uint32_t& b3,
                                       uint32_t addr) {
    asm volatile("ldmatrix.sync.aligned.m8n8.x4.trans.shared.b16 {%0,%1,%2,%3}, [%4];"
                 : "=r"(b0), "=r"(b1), "=r"(b2), "=r"(b3) : "r"(addr));
}
#define CP_COMMIT() asm volatile("cp.async.commit_group;" ::: "memory")
#define CP_WAIT3()  asm volatile("cp.async.wait_group 3;" ::: "memory")
#define CP_WAIT5()  asm volatile("cp.async.wait_group 5;" ::: "memory")

// ---------------------------------------------------------------------------
__global__ void embed_kernel(const float* __restrict__ state,
                             const float* __restrict__ ew,
                             const float* __restrict__ eb) {
    int idx = blockIdx.x * blockDim.x + threadIdx.x;
    int b = idx >> 8;
    int j = (idx & 255) * 2;
    float s0 = eb[j], s1 = eb[j + 1];
    const float* sp = state + b * STATE;
#pragma unroll 8
    for (int k = 0; k < STATE; k++) {
        float sv = sp[k];
        s0 = fmaf(sv, ew[k * H + j], s0);
        s1 = fmaf(sv, ew[k * H + j + 1], s1);
    }
    g_h0[idx] = pack_h2(tanhf(s0), tanhf(s1));
}

// ---------------------------------------------------------------------------
// fp16 m16n8k16 split-K GEMM, 256x128 CTA tile, 512 threads (16 warps 4x4).
// PAIRED sync units: one group bar.sync + one wait_group per 2 chunks
// (converts run 2 stages ahead in a 4-deep h2 quad buffer).
// ---------------------------------------------------------------------------
__global__ void __launch_bounds__(512, 1)
gemm_fp16(int layer, const float* __restrict__ cmd,
          const float* __restrict__ hwW, const float* __restrict__ hwb)
{
    extern __shared__ __align__(16) uint32_t smu[];
    uint32_t* sSc = smu;

    const int t    = threadIdx.x;
    const int lane = t & 31;
    const int wm   = (t >> 5) & 3;   // 0..3 -> 64-row group
    const int wn   = t >> 7;         // 0..3 -> 32-col group (contiguous 128 thr)
    const int tg   = t & 127;
    const int q    = lane & 3;
    const int r4   = lane >> 2;

    const int n0 = blockIdx.x * 128;
    const int m0 = blockIdx.y * 256;
    const int sp = blockIdx.z;
    const int c0  = sp * 7 + (sp < 3 ? sp : 3);
    const int cnt = 7 + (sp < 3 ? 1 : 0);

    const uint32_t* __restrict__ inh = layer ? g_h1 : g_h0;

    // ---- scale table: rec(ci, wm*8+r4) = 8 u32 dup-h2 ----
    if (t < cnt * 32) {
        int ci = t >> 5, rec = t & 31;
        int wmv = rec >> 3, rv = rec & 7;
        int d = c0 + ci;
        uint32_t* dst = sSc + (size_t)t * 8;
#pragma unroll
        for (int mi = 0; mi < 4; mi++) {
            int row0 = m0 + wmv * 64 + mi * 16 + rv;
            dst[mi * 2]     = dup_h2((d < DES) ? cmd[row0 * DES + d] : 1.0f);
            dst[mi * 2 + 1] = dup_h2((d < DES) ? cmd[(row0 + 8) * DES + d] : 1.0f);
        }
    }
    __syncthreads();

    const uint32_t base = smem_u32(smu);

    // ---- group-private fp32 ring (thread-private roundtrip) ----
    const int krow_cp = tg >> 3;
    const int nco = (tg & 7) * 4;
    const uint32_t ringp = base + RING_OFF + (uint32_t)wn * GROUP_RING;
    const uint32_t rdst = ringp + (uint32_t)(krow_cp * 32 + nco) * 4;

    // ---- group-private h2 quad buffer ----
    const uint32_t h2p = base + H2_OFF + (uint32_t)wn * GROUP_H2;
    const uint32_t csts = h2p + (uint32_t)krow_cp * H2ROW + (uint32_t)(tg & 7) * 8;
    const int sel  = lane >> 3;
    const int krow = ((sel & 1) << 3) | (lane & 7);
    const uint32_t ldm0 = h2p + (uint32_t)krow * H2ROW + (uint32_t)((sel >> 1) << 4);

    const int gcol = n0 + wn * 32 + nco;

    auto issueB = [&](int kbj, int cij, int slot) {
        int d = c0 + cij;
        const float* bb = ((d < DES) ? (hwW + (size_t)d * (H * H)) : hwb)
                          + ((size_t)(kbj * 16 + krow_cp)) * H + gcol;
        cp16(rdst + (uint32_t)slot * 2048, bb);
        CP_COMMIT();
    };
    auto convert = [&](int stage) {
        float4 v = lds128f(rdst + (uint32_t)(stage & 7) * 2048);
        sts64(csts + (uint32_t)(stage & 3) * H2BUF, pack_h2(v.x, v.y), pack_h2(v.z, v.w));
    };

    float acc[4][4][4];
#pragma unroll
    for (int i = 0; i < 4; i++)
#pragma unroll
        for (int j = 0; j < 4; j++)
#pragma unroll
            for (int k = 0; k < 4; k++) acc[i][j][k] = 0.0f;

    // prologue: issue 7 stages; convert stages 0,1
    int kb_is = 0, ci_is = 0;
#pragma unroll
    for (int i = 0; i < 7; i++) {
        issueB(kb_is, ci_is, i);
        if (++ci_is == cnt) { ci_is = 0; ++kb_is; }
    }
    CP_WAIT5();
    convert(0);
    convert(1);

    const uint32_t* aptr = inh + (size_t)(m0 + wm * 64 + r4) * (H / 2) + q;
    const uint32_t screc = (uint32_t)(wm * 8 + r4) * 8;

    uint32_t auf[4][4];
    int use_st = 0;      // current consume stage
    int conv_st = 2;     // next stage to convert
    int iss_slot = 7;    // ring slot for next issue

    for (int kb = 0; kb < 32; kb++) {
        // A band (h2) from gmem (L2-hot)
#pragma unroll
        for (int mi = 0; mi < 4; mi++) {
            const uint32_t* p = aptr + (size_t)(mi * 16) * (H / 2) + kb * 8;
            auf[mi][0] = p[0];
            auf[mi][1] = p[8 * (H / 2)];
            auf[mi][2] = p[4];
            auf[mi][3] = p[8 * (H / 2) + 4];
        }

        // 4 sync units per k-band: cnt=8 -> {2,2,2,2}; cnt=7 -> {2,2,2,1}
        for (int u = 0; u < 4; u++) {
            const int su = (u < 3) ? 2 : (cnt - 6);

            // unit-start barrier: makes converts of prev unit visible AND
            // licenses overwrite of bufs consumed >= 1 unit ago
            asm volatile("bar.sync %0, %1;" :: "r"(1 + wn), "r"(128) : "memory");
            CP_WAIT3();

            // convert su stages (conv = use + 2 invariant)
#pragma unroll
            for (int j = 0; j < 2; j++)
                if (j < su) { convert(conv_st); conv_st++; }

            // keep ring 7 ahead
#pragma unroll
            for (int j = 0; j < 2; j++)
                if (j < su) {
                    issueB(kb_is, ci_is, iss_slot & 7);
                    iss_slot++;
                    if (++ci_is == cnt) {
                        ci_is = 0;
                        if (++kb_is == 32) { kb_is = 31; ci_is = cnt - 1; }
                    }
                }

            // consume su chunks (both h2 bufs already visible -> ldsm of the
            // 2nd chunk overlaps the 1st chunk's MMA run)
#pragma unroll
            for (int j = 0; j < 2; j++) {
                if (j < su) {
                    const int ci = u * 2 + j;

                    const uint4* rec = (const uint4*)(sSc + ((uint32_t)ci * 32 * 8 + screc));
                    uint4 sA01 = rec[0];
                    uint4 sA23 = rec[1];
                    uint32_t sv[8] = {sA01.x, sA01.y, sA01.z, sA01.w,
                                      sA23.x, sA23.y, sA23.z, sA23.w};

                    uint32_t bf[4][2];
                    {
                        uint32_t a0 = ldm0 + (uint32_t)(use_st & 3) * H2BUF;
                        ldsm4t(bf[0][0], bf[0][1], bf[1][0], bf[1][1], a0);
                        ldsm4t(bf[2][0], bf[2][1], bf[3][0], bf[3][1], a0 + 32);
                    }

#pragma unroll
                    for (int mi = 0; mi < 4; mi++) {
                        uint32_t s0 = sv[mi * 2], s1 = sv[mi * 2 + 1];
                        uint32_t a0 = hmul2(auf[mi][0], s0);
                        uint32_t a1 = hmul2(auf[mi][1], s1);
                        uint32_t a2 = hmul2(auf[mi][2], s0);
                        uint32_t a3 = hmul2(auf[mi][3], s1);
#pragma unroll
                        for (int ni = 0; ni < 4; ni++)
                            mma16816(acc[mi][ni], a0, a1, a2, a3, bf[ni][0], bf[ni][1]);
                    }
                    use_st++;
                }
            }
        }
    }

    // epilogue
#pragma unroll
    for (int mi = 0; mi < 4; mi++) {
#pragma unroll
        for (int ni = 0; ni < 4; ni++) {
            int row = m0 + wm * 64 + mi * 16 + r4;
            int col = n0 + wn * 32 + ni * 8 + q * 2;
            *(float2*)&g_part[sp][row][col]     = make_float2(acc[mi][ni][0], acc[mi][ni][1]);
            *(float2*)&g_part[sp][row + 8][col] = make_float2(acc[mi][ni][2], acc[mi][ni][3]);
        }
    }
}

// ---------------------------------------------------------------------------
__global__ void reduce_bias_relu(const float* __restrict__ cmd,
                                 const float* __restrict__ hbW,
                                 const float* __restrict__ hbb,
                                 float* dst, int to_h1) {
    int idx = blockIdx.x * blockDim.x + threadIdx.x;
    int b = idx >> 8;
    int o = (idx & 255) * 2;
    float s0 = hbb[o], s1 = hbb[o + 1];
#pragma unroll
    for (int sp = 0; sp < SPLITS; sp++) {
        float2 v = *(const float2*)&g_part[sp][b][o];
        s0 += v.x; s1 += v.y;
    }
    const float* cp = cmd + b * DES;
#pragma unroll 16
    for (int k = 0; k < DES; k++) {
        float cv = cp[k];
        s0 = fmaf(cv, hbW[k * H + o], s0);
        s1 = fmaf(cv, hbW[k * H + o + 1], s1);
    }
    float r0 = fmaxf(s0, 0.0f);
    float r1 = fmaxf(s1, 0.0f);
    if (to_h1) {
        g_h1[idx] = pack_h2(r0, r1);
    } else {
        *(float2*)&dst[b * H + o] = make_float2(r0, r1);
    }
}

// ---------------------------------------------------------------------------
extern "C" void kernel_launch(void* const* d_in, const int* in_sizes, int n_in,
                              void* d_out, int out_size) {
    const float* state = (const float*)d_in[0];
    const float* cmd   = (const float*)d_in[1];
    const float* ew    = (const float*)d_in[2];
    const float* eb    = (const float*)d_in[3];
    const float* hwW   = (const float*)d_in[4];
    const float* hwb   = (const float*)d_in[5];
    const float* hbW   = (const float*)d_in[6];
    const float* hbb   = (const float*)d_in[7];
    float* out = (float*)d_out;

    const size_t HWW_L = (size_t)DES * H * H;
    const size_t HWB_L = (size_t)H * H;
    const size_t HBW_L = (size_t)DES * H;
    const size_t HBB_L = (size_t)H;

    static int smem_set = 0;
    if (!smem_set) {
        cudaFuncSetAttribute(gemm_fp16, cudaFuncAttributeMaxDynamicSharedMemorySize, SMEM_BYTES);
        smem_set = 1;
    }

    embed_kernel<<<512, 256>>>(state, ew, eb);

    dim3 grid(4, 2, SPLITS);

    gemm_fp16<<<grid, 512, SMEM_BYTES>>>(0, cmd, hwW, hwb);
    reduce_bias_relu<<<512, 256>>>(cmd, hbW, hbb, out, 1);

    gemm_fp16<<<grid, 512, SMEM_BYTES>>>(1, cmd, hwW + HWW_L, hwb + HWB_L);
    reduce_bias_relu<<<512, 256>>>(cmd, hbW + HBW_L, hbb + HBB_L, out, 0);
}